// round 1
// baseline (speedup 1.0000x reference)
#include <cuda_runtime.h>

#define B_   32
#define C_   3072
#define K_   11
#define HW_  784
#define NC_  200

// d_out layout: [afm (B,C,K)][scores (B,NC)][maps (B,K,HW)][attn (B,K)]
#define OFF_SCORES 1081344
#define OFF_MAPS   1087744
#define OFF_ATTN   1363712

__device__ float g_asq[16];
__device__ float g_f[B_ * C_];

// ---------------------------------------------------------------------------
// a_sq[k] = sum_c w_land[k,c]^2   (1 block, 11 warps)
// ---------------------------------------------------------------------------
__global__ void asq_kernel(const float* __restrict__ wl) {
    int k = threadIdx.x >> 5, lane = threadIdx.x & 31;
    if (k >= K_) return;
    const float* row = wl + k * C_;
    float s = 0.f;
    for (int c = lane; c < C_; c += 32) { float v = row[c]; s = fmaf(v, v, s); }
    #pragma unroll
    for (int o = 16; o; o >>= 1) s += __shfl_xor_sync(0xffffffffu, s, o);
    if (lane == 0) g_asq[k] = s;
}

// ---------------------------------------------------------------------------
// maps kernel: logits_k = 2*<x_pixel, w_k> - a_sq_k ; softmax over k.
// 196 blocks x 512 threads. Each block: 128 pixels, C split into 4 segments of
// 768 handled by thread groups (tid>>7), partial sums reduced through smem.
// w_land staged in smem per 192-channel chunk, padded to 12 floats per channel
// so the inner loop is 1 LDG + 3 LDS.128 + 11 FFMA.
// ---------------------------------------------------------------------------
#define MK_CHUNK 192
__global__ __launch_bounds__(512) void maps_kernel(
    const float* __restrict__ x, const float* __restrict__ wl,
    float* __restrict__ maps)
{
    __shared__ __align__(16) float sw[4 * MK_CHUNK * 12];   // 36864 B
    int tid = threadIdx.x;
    int px  = tid & 127;
    int seg = tid >> 7;                  // 0..3 -> channel segment of 768
    int g   = blockIdx.x * 128 + px;     // global pixel id (exact: 196*128 = 25088)
    int b   = g / HW_;
    int hw  = g - b * HW_;
    const float* xp = x + (size_t)b * (C_ * HW_) + hw;

    float acc[K_];
    #pragma unroll
    for (int k = 0; k < K_; k++) acc[k] = 0.f;

    for (int ci = 0; ci < 4; ci++) {     // 4 chunks of 192 per segment
        __syncthreads();
        // cooperative stage: 4 segs x 11 k x 192 cc
        for (int idx = tid; idx < 4 * K_ * MK_CHUNK; idx += 512) {
            int s2 = idx / (K_ * MK_CHUNK);
            int r  = idx - s2 * (K_ * MK_CHUNK);
            int k  = r / MK_CHUNK;
            int cc = r - k * MK_CHUNK;
            sw[(s2 * MK_CHUNK + cc) * 12 + k] =
                wl[k * C_ + s2 * 768 + ci * MK_CHUNK + cc];
        }
        __syncthreads();
        const float* xseg = xp + (size_t)(seg * 768 + ci * MK_CHUNK) * HW_;
        const float* wseg = sw + seg * MK_CHUNK * 12;
        #pragma unroll 8
        for (int cc = 0; cc < MK_CHUNK; cc++) {
            float  xv = __ldg(xseg + (size_t)cc * HW_);
            float4 w0 = *(const float4*)(wseg + cc * 12);
            float4 w1 = *(const float4*)(wseg + cc * 12 + 4);
            float4 w2 = *(const float4*)(wseg + cc * 12 + 8);
            acc[0]  = fmaf(xv, w0.x, acc[0]);
            acc[1]  = fmaf(xv, w0.y, acc[1]);
            acc[2]  = fmaf(xv, w0.z, acc[2]);
            acc[3]  = fmaf(xv, w0.w, acc[3]);
            acc[4]  = fmaf(xv, w1.x, acc[4]);
            acc[5]  = fmaf(xv, w1.y, acc[5]);
            acc[6]  = fmaf(xv, w1.z, acc[6]);
            acc[7]  = fmaf(xv, w1.w, acc[7]);
            acc[8]  = fmaf(xv, w2.x, acc[8]);
            acc[9]  = fmaf(xv, w2.y, acc[9]);
            acc[10] = fmaf(xv, w2.z, acc[10]);
        }
    }
    __syncthreads();
    // cross-segment reduction through smem: [px][seg][12]
    #pragma unroll
    for (int k = 0; k < K_; k++) sw[(px * 4 + seg) * 12 + k] = acc[k];
    __syncthreads();
    if (seg == 0) {
        #pragma unroll
        for (int k = 0; k < K_; k++)
            acc[k] = sw[(px * 4 + 0) * 12 + k] + sw[(px * 4 + 1) * 12 + k]
                   + sw[(px * 4 + 2) * 12 + k] + sw[(px * 4 + 3) * 12 + k];
        // softmax over k of 2*ab - a_sq  (b_sq cancels: constant in k)
        float m = -1e30f;
        #pragma unroll
        for (int k = 0; k < K_; k++) {
            acc[k] = 2.f * acc[k] - g_asq[k];
            m = fmaxf(m, acc[k]);
        }
        float s = 0.f;
        #pragma unroll
        for (int k = 0; k < K_; k++) { acc[k] = __expf(acc[k] - m); s += acc[k]; }
        float inv = 1.f / s;
        float* mp = maps + (size_t)b * (K_ * HW_) + hw;
        #pragma unroll
        for (int k = 0; k < K_; k++) mp[k * HW_] = acc[k] * inv;
    }
}

// ---------------------------------------------------------------------------
// feature kernel: afm[b,c,k] = (sum_hw maps[b,k,hw]*x[b,c,hw])/784 * mod[c,k]
// Also f[b,c] = sum_k afm[b,c,k] (scratch for scores).
// grid (48, B): block owns (b, 64 channels); 8 warps x 4 pairs of channels.
// Warp lanes span HW (float4), maps tile lives in smem (padded row 800).
// ---------------------------------------------------------------------------
__global__ __launch_bounds__(256) void feat_kernel(
    const float* __restrict__ x, const float* __restrict__ maps,
    const float* __restrict__ mod, float* __restrict__ afm)
{
    __shared__ __align__(16) float sm[K_ * 800];   // 35200 B
    int b = blockIdx.y;
    const float* mp = maps + (size_t)b * (K_ * HW_);
    for (int idx = threadIdx.x; idx < K_ * HW_; idx += 256) {
        int k  = idx / HW_;
        int hw = idx - k * HW_;
        sm[k * 800 + hw] = mp[idx];
    }
    __syncthreads();
    int warp = threadIdx.x >> 5, lane = threadIdx.x & 31;
    #pragma unroll 1
    for (int pair = 0; pair < 4; pair++) {
        int c0 = blockIdx.x * 64 + warp * 8 + pair * 2;
        const float* xp0 = x + ((size_t)b * C_ + c0) * HW_;
        const float* xp1 = xp0 + HW_;
        float a0[K_], a1[K_];
        #pragma unroll
        for (int k = 0; k < K_; k++) { a0[k] = 0.f; a1[k] = 0.f; }
        for (int i = 0; i < 7; i++) {
            int hw = i * 128 + lane * 4;
            if (hw < HW_) {
                float4 x0 = *(const float4*)(xp0 + hw);
                float4 x1 = *(const float4*)(xp1 + hw);
                #pragma unroll
                for (int k = 0; k < K_; k++) {
                    float4 mv = *(const float4*)(sm + k * 800 + hw);
                    a0[k] = fmaf(x0.x, mv.x, a0[k]);
                    a0[k] = fmaf(x0.y, mv.y, a0[k]);
                    a0[k] = fmaf(x0.z, mv.z, a0[k]);
                    a0[k] = fmaf(x0.w, mv.w, a0[k]);
                    a1[k] = fmaf(x1.x, mv.x, a1[k]);
                    a1[k] = fmaf(x1.y, mv.y, a1[k]);
                    a1[k] = fmaf(x1.z, mv.z, a1[k]);
                    a1[k] = fmaf(x1.w, mv.w, a1[k]);
                }
            }
        }
        #pragma unroll
        for (int k = 0; k < K_; k++) {
            #pragma unroll
            for (int o = 16; o; o >>= 1) {
                a0[k] += __shfl_xor_sync(0xffffffffu, a0[k], o);
                a1[k] += __shfl_xor_sync(0xffffffffu, a1[k], o);
            }
        }
        if (lane == 0) {
            const float inv = 1.f / (float)HW_;
            float f0 = 0.f, f1 = 0.f;
            float* o0 = afm + ((size_t)b * C_ + c0) * K_;
            #pragma unroll
            for (int k = 0; k < K_; k++) {
                float v0 = a0[k] * inv * mod[c0 * K_ + k];
                float v1 = a1[k] * inv * mod[(c0 + 1) * K_ + k];
                o0[k]      = v0;
                o0[K_ + k] = v1;
                f0 += v0;
                f1 += v1;
            }
            g_f[b * C_ + c0]     = f0;
            g_f[b * C_ + c0 + 1] = f1;
        }
    }
}

// ---------------------------------------------------------------------------
// attn[b,k] = sum_hw maps[b,k,hw]   (warp per (b,k))
// ---------------------------------------------------------------------------
__global__ __launch_bounds__(256) void attn_kernel(
    const float* __restrict__ maps, float* __restrict__ attn)
{
    int w = blockIdx.x * 8 + (threadIdx.x >> 5);
    int lane = threadIdx.x & 31;
    if (w >= B_ * K_) return;
    const float* mp = maps + (size_t)w * HW_;
    float s = 0.f;
    for (int hw = lane * 4; hw < HW_; hw += 128) {
        float4 v = *(const float4*)(mp + hw);
        s += v.x + v.y + v.z + v.w;
    }
    #pragma unroll
    for (int o = 16; o; o >>= 1) s += __shfl_xor_sync(0xffffffffu, s, o);
    if (lane == 0) attn[w] = s;
}

// ---------------------------------------------------------------------------
// scores[b,n] = sum_c f[b,c] * w_cls[n,c]   (grid (7,B), warp handles 4 n's)
// ---------------------------------------------------------------------------
__global__ __launch_bounds__(256) void score_kernel(
    const float* __restrict__ wcls, float* __restrict__ scores)
{
    __shared__ __align__(16) float sf[C_];
    int b = blockIdx.y;
    for (int idx = threadIdx.x; idx < C_; idx += 256) sf[idx] = g_f[b * C_ + idx];
    __syncthreads();
    int warp = threadIdx.x >> 5, lane = threadIdx.x & 31;
    #pragma unroll 1
    for (int j = 0; j < 4; j++) {
        int n = blockIdx.x * 32 + warp * 4 + j;
        if (n < NC_) {
            const float* wr = wcls + (size_t)n * C_;
            float s = 0.f;
            for (int c = lane * 4; c < C_; c += 128) {
                float4 wv = *(const float4*)(wr + c);
                float4 fv = *(const float4*)(sf + c);
                s = fmaf(wv.x, fv.x, s);
                s = fmaf(wv.y, fv.y, s);
                s = fmaf(wv.z, fv.z, s);
                s = fmaf(wv.w, fv.w, s);
            }
            #pragma unroll
            for (int o = 16; o; o >>= 1) s += __shfl_xor_sync(0xffffffffu, s, o);
            if (lane == 0) scores[b * NC_ + n] = s;
        }
    }
}

// ---------------------------------------------------------------------------
extern "C" void kernel_launch(void* const* d_in, const int* in_sizes, int n_in,
                              void* d_out, int out_size) {
    const float* x    = (const float*)d_in[0];   // (B,C,H,W)
    const float* wl   = (const float*)d_in[1];   // (K,C)
    const float* mod  = (const float*)d_in[2];   // (1,C,K)
    const float* wcls = (const float*)d_in[3];   // (NC,C)
    float* out    = (float*)d_out;
    float* afm    = out;
    float* scores = out + OFF_SCORES;
    float* maps   = out + OFF_MAPS;
    float* attn   = out + OFF_ATTN;

    asq_kernel<<<1, 352>>>(wl);
    maps_kernel<<<196, 512>>>(x, wl, maps);
    feat_kernel<<<dim3(48, B_), 256>>>(x, maps, mod, afm);
    attn_kernel<<<44, 256>>>(maps, attn);
    score_kernel<<<dim3(7, B_), 256>>>(wcls, scores);
}

// round 2
// speedup vs baseline: 1.1040x; 1.1040x over previous
#include <cuda_runtime.h>

#define B_   32
#define C_   3072
#define K_   11
#define HW_  784
#define NC_  200

// d_out layout: [afm (B,C,K)][scores (B,NC)][maps (B,K,HW)][attn (B,K)]
#define OFF_SCORES 1081344
#define OFF_MAPS   1087744
#define OFF_ATTN   1363712

__device__ float g_asq[16];
__device__ float g_f[B_ * C_];

typedef unsigned long long u64;

__device__ __forceinline__ u64 pk(float a, float b) {
    u64 r; asm("mov.b64 %0,{%1,%2};" : "=l"(r) : "f"(a), "f"(b)); return r;
}
__device__ __forceinline__ float2 upk(u64 a) {
    float2 f; asm("mov.b64 {%0,%1},%2;" : "=f"(f.x), "=f"(f.y) : "l"(a)); return f;
}
__device__ __forceinline__ void fma2(u64& d, u64 a, u64 b) {
    asm("fma.rn.f32x2 %0,%1,%2,%0;" : "+l"(d) : "l"(a), "l"(b));
}
__device__ __forceinline__ u64 add2(u64 a, u64 b) {
    u64 r; asm("add.rn.f32x2 %0,%1,%2;" : "=l"(r) : "l"(a), "l"(b)); return r;
}

// ---------------------------------------------------------------------------
// a_sq[k] = sum_c w_land[k,c]^2   (1 block, 11 warps)
// ---------------------------------------------------------------------------
__global__ void asq_kernel(const float* __restrict__ wl) {
    int k = threadIdx.x >> 5, lane = threadIdx.x & 31;
    if (k >= K_) return;
    const float* row = wl + k * C_;
    float s = 0.f;
    for (int c = lane; c < C_; c += 32) { float v = row[c]; s = fmaf(v, v, s); }
    #pragma unroll
    for (int o = 16; o; o >>= 1) s += __shfl_xor_sync(0xffffffffu, s, o);
    if (lane == 0) g_asq[k] = s;
}

// ---------------------------------------------------------------------------
// maps kernel v2: logits_k = 2*<x_pixel, w_k> - a_sq_k ; softmax over k.
// 392 blocks x 256 threads. Each thread: 4 pixels (one quad, via LDG.128),
// one of 16 channel segments (192 ch each). f32x2 packed accumulation.
// Per channel: 1 LDG.128 + 3 LDS.128 + 13 ALU packs + 22 FFMA2 (4 pixels).
// ---------------------------------------------------------------------------
#define MSEGS 16
#define MSEGC 192
#define MCH   48
#define MQPB  16
__global__ __launch_bounds__(256, 2) void maps_kernel(
    const float* __restrict__ x, const float* __restrict__ wl,
    float* __restrict__ maps)
{
    __shared__ __align__(16) float sraw[MSEGS * MCH * 12];   // 36864 B
    int tid  = threadIdx.x;
    int q    = tid & 15;          // quad within block
    int seg  = tid >> 4;          // 0..15 channel segment
    int gq   = blockIdx.x * MQPB + q;       // global quad, 0..6271
    int b    = gq / 196;
    int hw0  = (gq - b * 196) * 4;
    const float* xp = x + (size_t)b * (C_ * HW_) + (size_t)(seg * MSEGC) * HW_ + hw0;

    u64 accA[K_], accB[K_];
    #pragma unroll
    for (int k = 0; k < K_; k++) { accA[k] = 0ull; accB[k] = 0ull; }

    for (int ci = 0; ci < 4; ci++) {
        __syncthreads();
        for (int idx = tid; idx < MSEGS * MCH * K_; idx += 256) {   // 8448
            int k  = idx / (MSEGS * MCH);
            int r  = idx - k * (MSEGS * MCH);
            int s2 = r / MCH;
            int cc = r - s2 * MCH;
            sraw[(s2 * MCH + cc) * 12 + k] = wl[k * C_ + s2 * MSEGC + ci * MCH + cc];
        }
        __syncthreads();
        const float*  xc   = xp + (size_t)(ci * MCH) * HW_;
        const float4* wrow = (const float4*)(sraw + seg * MCH * 12);
        #pragma unroll 4
        for (int cc = 0; cc < MCH; cc++) {
            float4 xv = *(const float4*)(xc + (size_t)cc * HW_);
            float4 w0 = wrow[cc * 3 + 0];
            float4 w1 = wrow[cc * 3 + 1];
            float4 w2 = wrow[cc * 3 + 2];
            u64 xA = pk(xv.x, xv.y);
            u64 xB = pk(xv.z, xv.w);
            u64 wp;
            wp = pk(w0.x, w0.x); fma2(accA[0],  xA, wp); fma2(accB[0],  xB, wp);
            wp = pk(w0.y, w0.y); fma2(accA[1],  xA, wp); fma2(accB[1],  xB, wp);
            wp = pk(w0.z, w0.z); fma2(accA[2],  xA, wp); fma2(accB[2],  xB, wp);
            wp = pk(w0.w, w0.w); fma2(accA[3],  xA, wp); fma2(accB[3],  xB, wp);
            wp = pk(w1.x, w1.x); fma2(accA[4],  xA, wp); fma2(accB[4],  xB, wp);
            wp = pk(w1.y, w1.y); fma2(accA[5],  xA, wp); fma2(accB[5],  xB, wp);
            wp = pk(w1.z, w1.z); fma2(accA[6],  xA, wp); fma2(accB[6],  xB, wp);
            wp = pk(w1.w, w1.w); fma2(accA[7],  xA, wp); fma2(accB[7],  xB, wp);
            wp = pk(w2.x, w2.x); fma2(accA[8],  xA, wp); fma2(accB[8],  xB, wp);
            wp = pk(w2.y, w2.y); fma2(accA[9],  xA, wp); fma2(accB[9],  xB, wp);
            wp = pk(w2.z, w2.z); fma2(accA[10], xA, wp); fma2(accB[10], xB, wp);
        }
    }

    // fold the two segments that share a warp (lanes 0-15 <-> 16-31)
    #pragma unroll
    for (int k = 0; k < K_; k++) {
        accA[k] = add2(accA[k], __shfl_xor_sync(0xffffffffu, accA[k], 16));
        accB[k] = add2(accB[k], __shfl_xor_sync(0xffffffffu, accB[k], 16));
    }
    int warp = tid >> 5, lane = tid & 31;
    __syncthreads();
    // red layout: [8 warps][16 quads][2 pairs][12 k] float2 = 24576 B
    float2* red = (float2*)sraw;
    if (lane < 16) {
        int base = ((warp * 16 + lane) * 2) * 12;
        #pragma unroll
        for (int k = 0; k < K_; k++) {
            red[base + k]      = upk(accA[k]);
            red[base + 12 + k] = upk(accB[k]);
        }
    }
    __syncthreads();
    if (tid < 64) {
        int quad = tid >> 2, px = tid & 3;
        int pair = px >> 1, half = px & 1;
        float lg[K_];
        #pragma unroll
        for (int k = 0; k < K_; k++) {
            float s = 0.f;
            #pragma unroll
            for (int w = 0; w < 8; w++) {
                float2 v = red[((w * 16 + quad) * 2 + pair) * 12 + k];
                s += half ? v.y : v.x;
            }
            lg[k] = s;
        }
        float m = -1e30f;
        #pragma unroll
        for (int k = 0; k < K_; k++) {
            lg[k] = 2.f * lg[k] - g_asq[k];
            m = fmaxf(m, lg[k]);
        }
        float s = 0.f;
        #pragma unroll
        for (int k = 0; k < K_; k++) { lg[k] = __expf(lg[k] - m); s += lg[k]; }
        float inv = 1.f / s;
        int gq2 = blockIdx.x * MQPB + quad;
        int b2  = gq2 / 196;
        int hw  = (gq2 - b2 * 196) * 4 + px;
        float* mp = maps + (size_t)b2 * (K_ * HW_) + hw;
        #pragma unroll
        for (int k = 0; k < K_; k++) mp[k * HW_] = lg[k] * inv;
    }
}

// ---------------------------------------------------------------------------
// feature kernel v2: afm[b,c,k] = (sum_hw maps[b,k,hw]*x[b,c,hw])/784 * mod[c,k]
// f[b,c] = sum_k afm. f32x2 accumulation via ulonglong2 reinterpretation.
// grid (48, B), 256 threads: 8 warps x 4 pairs of channels.
// blockIdx.x==0 also computes attn[b,k] = sum_hw maps (tile already in smem).
// ---------------------------------------------------------------------------
__global__ __launch_bounds__(256) void feat_kernel(
    const float* __restrict__ x, const float* __restrict__ maps,
    const float* __restrict__ mod, float* __restrict__ afm,
    float* __restrict__ attn)
{
    __shared__ __align__(16) float sm[K_ * 800];   // 35200 B
    int b = blockIdx.y;
    const float* mp = maps + (size_t)b * (K_ * HW_);
    for (int idx = threadIdx.x; idx < K_ * HW_; idx += 256) {
        int k  = idx / HW_;
        int hw = idx - k * HW_;
        sm[k * 800 + hw] = mp[idx];
    }
    __syncthreads();
    int warp = threadIdx.x >> 5, lane = threadIdx.x & 31;

    if (blockIdx.x == 0) {   // fold attn into this kernel
        for (int k = warp; k < K_; k += 8) {
            float s = 0.f;
            for (int hw = lane; hw < HW_; hw += 32) s += sm[k * 800 + hw];
            #pragma unroll
            for (int o = 16; o; o >>= 1) s += __shfl_xor_sync(0xffffffffu, s, o);
            if (lane == 0) attn[b * K_ + k] = s;
        }
    }

    #pragma unroll 1
    for (int pair = 0; pair < 4; pair++) {
        int c0 = blockIdx.x * 64 + warp * 8 + pair * 2;
        const float* xp0 = x + ((size_t)b * C_ + c0) * HW_;
        const float* xp1 = xp0 + HW_;
        u64 a0[K_], a1[K_];
        #pragma unroll
        for (int k = 0; k < K_; k++) { a0[k] = 0ull; a1[k] = 0ull; }
        #pragma unroll 1
        for (int i = 0; i < 7; i++) {
            int hw = i * 128 + lane * 4;
            if (hw < HW_) {
                ulonglong2 x0 = *(const ulonglong2*)(xp0 + hw);
                ulonglong2 x1 = *(const ulonglong2*)(xp1 + hw);
                #pragma unroll
                for (int k = 0; k < K_; k++) {
                    ulonglong2 mv = *(const ulonglong2*)(sm + k * 800 + hw);
                    fma2(a0[k], x0.x, mv.x);
                    fma2(a0[k], x0.y, mv.y);
                    fma2(a1[k], x1.x, mv.x);
                    fma2(a1[k], x1.y, mv.y);
                }
            }
        }
        float s0[K_], s1[K_];
        #pragma unroll
        for (int k = 0; k < K_; k++) {
            float2 v0 = upk(a0[k]); s0[k] = v0.x + v0.y;
            float2 v1 = upk(a1[k]); s1[k] = v1.x + v1.y;
            #pragma unroll
            for (int o = 16; o; o >>= 1) {
                s0[k] += __shfl_xor_sync(0xffffffffu, s0[k], o);
                s1[k] += __shfl_xor_sync(0xffffffffu, s1[k], o);
            }
        }
        if (lane == 0) {
            const float inv = 1.f / (float)HW_;
            float f0 = 0.f, f1 = 0.f;
            float* o0 = afm + ((size_t)b * C_ + c0) * K_;
            #pragma unroll
            for (int k = 0; k < K_; k++) {
                float v0 = s0[k] * inv * mod[c0 * K_ + k];
                float v1 = s1[k] * inv * mod[(c0 + 1) * K_ + k];
                o0[k]      = v0;
                o0[K_ + k] = v1;
                f0 += v0;
                f1 += v1;
            }
            g_f[b * C_ + c0]     = f0;
            g_f[b * C_ + c0 + 1] = f1;
        }
    }
}

// ---------------------------------------------------------------------------
// scores[b,n] = sum_c f[b,c] * w_cls[n,c]   (grid (7,B), warp handles 4 n's)
// ---------------------------------------------------------------------------
__global__ __launch_bounds__(256) void score_kernel(
    const float* __restrict__ wcls, float* __restrict__ scores)
{
    __shared__ __align__(16) float sf[C_];
    int b = blockIdx.y;
    for (int idx = threadIdx.x; idx < C_; idx += 256) sf[idx] = g_f[b * C_ + idx];
    __syncthreads();
    int warp = threadIdx.x >> 5, lane = threadIdx.x & 31;
    #pragma unroll 1
    for (int j = 0; j < 4; j++) {
        int n = blockIdx.x * 32 + warp * 4 + j;
        if (n < NC_) {
            const float* wr = wcls + (size_t)n * C_;
            float s = 0.f;
            for (int c = lane * 4; c < C_; c += 128) {
                float4 wv = *(const float4*)(wr + c);
                float4 fv = *(const float4*)(sf + c);
                s = fmaf(wv.x, fv.x, s);
                s = fmaf(wv.y, fv.y, s);
                s = fmaf(wv.z, fv.z, s);
                s = fmaf(wv.w, fv.w, s);
            }
            #pragma unroll
            for (int o = 16; o; o >>= 1) s += __shfl_xor_sync(0xffffffffu, s, o);
            if (lane == 0) scores[b * NC_ + n] = s;
        }
    }
}

// ---------------------------------------------------------------------------
extern "C" void kernel_launch(void* const* d_in, const int* in_sizes, int n_in,
                              void* d_out, int out_size) {
    const float* x    = (const float*)d_in[0];   // (B,C,H,W)
    const float* wl   = (const float*)d_in[1];   // (K,C)
    const float* mod  = (const float*)d_in[2];   // (1,C,K)
    const float* wcls = (const float*)d_in[3];   // (NC,C)
    float* out    = (float*)d_out;
    float* afm    = out;
    float* scores = out + OFF_SCORES;
    float* maps   = out + OFF_MAPS;
    float* attn   = out + OFF_ATTN;

    asq_kernel<<<1, 352>>>(wl);
    maps_kernel<<<392, 256>>>(x, wl, maps);
    feat_kernel<<<dim3(48, B_), 256>>>(x, maps, mod, afm, attn);
    score_kernel<<<dim3(7, B_), 256>>>(wcls, scores);
}